// round 1
// baseline (speedup 1.0000x reference)
#include <cuda_runtime.h>
#include <math.h>

#define IN_DIM  20
#define HID     6
#define OUT_DIM 6

__device__ __forceinline__ float fast_sigmoid(float z) {
    // 1 / (1 + e^{-z}) : MUFU.EX2 + FMUL + FADD + MUFU.RCP
    return __fdividef(1.0f, 1.0f + __expf(-z));
}

__global__ __launch_bounds__(256)
void mlp3_kernel(const float* __restrict__ x,
                 const float* __restrict__ W1,   // [HID, IN]
                 const float* __restrict__ W2,   // [HID, HID]
                 const float* __restrict__ W5,   // [OUT, HID]
                 float* __restrict__ out,        // [B, OUT]
                 int B)
{
    // Hoist all weights into registers (uniform-address LDGs, broadcast within warp,
    // amortized across the grid-stride loop).
    float w1[HID][IN_DIM];
    float w2[HID][HID];
    float w5[OUT_DIM][HID];

#pragma unroll
    for (int j = 0; j < HID; ++j)
#pragma unroll
        for (int k = 0; k < IN_DIM; ++k)
            w1[j][k] = __ldg(&W1[j * IN_DIM + k]);

#pragma unroll
    for (int j = 0; j < HID; ++j)
#pragma unroll
        for (int k = 0; k < HID; ++k)
            w2[j][k] = __ldg(&W2[j * HID + k]);

#pragma unroll
    for (int j = 0; j < OUT_DIM; ++j)
#pragma unroll
        for (int k = 0; k < HID; ++k)
            w5[j][k] = __ldg(&W5[j * HID + k]);

    const int stride = gridDim.x * blockDim.x;

    for (int r = blockIdx.x * blockDim.x + threadIdx.x; r < B; r += stride) {
        // ---- load one row of x: 80 bytes, 16B-aligned -> 5x LDG.128 ----
        float xi[IN_DIM];
        const float4* xr = reinterpret_cast<const float4*>(x + (size_t)r * IN_DIM);
#pragma unroll
        for (int q = 0; q < IN_DIM / 4; ++q) {
            float4 v = xr[q];
            xi[4 * q + 0] = v.x;
            xi[4 * q + 1] = v.y;
            xi[4 * q + 2] = v.z;
            xi[4 * q + 3] = v.w;
        }

        // ---- layer 1: [20] -> [6], sigmoid ----
        float h1[HID];
#pragma unroll
        for (int j = 0; j < HID; ++j) {
            float a = 0.0f;
#pragma unroll
            for (int k = 0; k < IN_DIM; ++k)
                a = fmaf(xi[k], w1[j][k], a);
            h1[j] = fast_sigmoid(a);
        }

        // ---- layer 2: [6] -> [6], sigmoid ----
        float h2[HID];
#pragma unroll
        for (int j = 0; j < HID; ++j) {
            float a = 0.0f;
#pragma unroll
            for (int k = 0; k < HID; ++k)
                a = fmaf(h1[k], w2[j][k], a);
            h2[j] = fast_sigmoid(a);
        }

        // ---- layer 3: [6] -> [6], linear ----
        float o[OUT_DIM];
#pragma unroll
        for (int j = 0; j < OUT_DIM; ++j) {
            float a = 0.0f;
#pragma unroll
            for (int k = 0; k < HID; ++k)
                a = fmaf(h2[k], w5[j][k], a);
            o[j] = a;
        }

        // ---- store 24 bytes, 8B-aligned -> 3x STG.64 ----
        float2* op = reinterpret_cast<float2*>(out + (size_t)r * OUT_DIM);
        op[0] = make_float2(o[0], o[1]);
        op[1] = make_float2(o[2], o[3]);
        op[2] = make_float2(o[4], o[5]);
    }
}

extern "C" void kernel_launch(void* const* d_in, const int* in_sizes, int n_in,
                              void* d_out, int out_size)
{
    const float* x  = (const float*)d_in[0];
    const float* W1 = (const float*)d_in[1];
    const float* W2 = (const float*)d_in[2];
    const float* W5 = (const float*)d_in[3];
    float* out = (float*)d_out;

    const int B = in_sizes[0] / IN_DIM;

    const int threads = 256;
    // ~8 rows per thread: amortizes the 192 weight loads, keeps MLP high.
    int blocks = (B + threads * 8 - 1) / (threads * 8);
    if (blocks < 1) blocks = 1;

    mlp3_kernel<<<blocks, threads>>>(x, W1, W2, W5, out, B);
}

// round 2
// speedup vs baseline: 1.4923x; 1.4923x over previous
#include <cuda_runtime.h>

#define IN_DIM   20
#define HID      6
#define OUT_DIM  6
#define TILE_ROWS 256
#define THREADS   256

__device__ __forceinline__ unsigned smem_u32(const void* p) {
    return (unsigned)__cvta_generic_to_shared(p);
}
__device__ __forceinline__ void cp16(unsigned dst, const void* src) {
    asm volatile("cp.async.ca.shared.global [%0], [%1], 16;\n" :: "r"(dst), "l"(src));
}
__device__ __forceinline__ void cp_commit() {
    asm volatile("cp.async.commit_group;\n" ::: "memory");
}
template <int N>
__device__ __forceinline__ void cp_wait() {
    asm volatile("cp.async.wait_group %0;\n" :: "n"(N) : "memory");
}

__device__ __forceinline__ float sigmoidf_(float z) {
    return __fdividef(1.0f, 1.0f + __expf(-z));   // MUFU.EX2 + MUFU.RCP
}

__global__ __launch_bounds__(THREADS, 3)
void mlp3_kernel(const float* __restrict__ x,
                 const float* __restrict__ W1,   // [HID, IN]
                 const float* __restrict__ W2,   // [HID, HID]
                 const float* __restrict__ W5,   // [OUT, HID]
                 float* __restrict__ out,        // [B, OUT]
                 int B, int ntiles)
{
    __shared__ __align__(16) float sW1[HID * IN_DIM];   // [6][20], rows 80B (16B aligned)
    __shared__ __align__(16) float sW2[HID * 8];        // [6][8] zero-padded
    __shared__ __align__(16) float sW5[OUT_DIM * 8];    // [6][8] zero-padded
    __shared__ __align__(16) float sX[2][TILE_ROWS * IN_DIM];  // 2 x 20KB

    const int t = threadIdx.x;

    // ---- weights -> smem (once per block) ----
    if (t < HID * IN_DIM) sW1[t] = W1[t];
    if (t < HID * 8)      sW2[t] = ((t & 7) < HID) ? W2[(t >> 3) * HID + (t & 7)] : 0.0f;
    if (t < OUT_DIM * 8)  sW5[t] = ((t & 7) < HID) ? W5[(t >> 3) * HID + (t & 7)] : 0.0f;

    const size_t total_f4 = ((size_t)B * IN_DIM) >> 2;           // B*20/4
    const int f4_per_tile = TILE_ROWS * IN_DIM / 4;              // 1280

    // ---- stage tile `tile` into buffer `buf` (coalesced cp.async, 5x16B/thread) ----
    auto stage = [&](int tile, int buf) {
        size_t base_f4 = (size_t)tile * f4_per_tile;
        const float4* src = reinterpret_cast<const float4*>(x) + base_f4;
        unsigned dst = smem_u32(&sX[buf][0]);
#pragma unroll
        for (int q = 0; q < 5; ++q) {
            int idx = t + q * THREADS;
            if (base_f4 + (size_t)idx < total_f4)
                cp16(dst + (unsigned)idx * 16, src + idx);
        }
    };

    int tile = blockIdx.x;
    if (tile < ntiles) stage(tile, 0);
    cp_commit();

    __syncthreads();   // weights visible before first compute

    int buf = 0;
    for (; tile < ntiles; tile += gridDim.x, buf ^= 1) {
        // prefetch next tile into the other buffer
        int nxt = tile + gridDim.x;
        if (nxt < ntiles) stage(nxt, buf ^ 1);
        cp_commit();
        cp_wait<1>();          // current tile's group complete
        __syncthreads();

        const int row = tile * TILE_ROWS + t;
        if (row < B) {
            // ---- x row from smem: 5 conflict-free LDS.128 ----
            float4 xv[5];
            const float4* xr = reinterpret_cast<const float4*>(&sX[buf][t * IN_DIM]);
#pragma unroll
            for (int q = 0; q < 5; ++q) xv[q] = xr[q];

            // ---- layer 1: 20 -> 6, sigmoid ----
            float h1[8];
#pragma unroll
            for (int j = 0; j < HID; ++j) {
                const float4* wr = reinterpret_cast<const float4*>(&sW1[j * IN_DIM]);
                float a = 0.0f;
#pragma unroll
                for (int q = 0; q < 5; ++q) {
                    float4 w = wr[q];
                    a = fmaf(xv[q].x, w.x, a);
                    a = fmaf(xv[q].y, w.y, a);
                    a = fmaf(xv[q].z, w.z, a);
                    a = fmaf(xv[q].w, w.w, a);
                }
                h1[j] = sigmoidf_(a);
            }
            h1[6] = 0.0f; h1[7] = 0.0f;

            // ---- layer 2: 6 -> 6, sigmoid (padded dot-8) ----
            float h2[8];
#pragma unroll
            for (int j = 0; j < HID; ++j) {
                const float4* wr = reinterpret_cast<const float4*>(&sW2[j * 8]);
                float4 w0 = wr[0], w1 = wr[1];
                float a = 0.0f;
                a = fmaf(h1[0], w0.x, a); a = fmaf(h1[1], w0.y, a);
                a = fmaf(h1[2], w0.z, a); a = fmaf(h1[3], w0.w, a);
                a = fmaf(h1[4], w1.x, a); a = fmaf(h1[5], w1.y, a);
                h2[j] = sigmoidf_(a);
            }

            // ---- layer 3: 6 -> 6, linear ----
            float o[OUT_DIM];
#pragma unroll
            for (int j = 0; j < OUT_DIM; ++j) {
                const float4* wr = reinterpret_cast<const float4*>(&sW5[j * 8]);
                float4 w0 = wr[0], w1 = wr[1];
                float a = 0.0f;
                a = fmaf(h2[0], w0.x, a); a = fmaf(h2[1], w0.y, a);
                a = fmaf(h2[2], w0.z, a); a = fmaf(h2[3], w0.w, a);
                a = fmaf(h2[4], w1.x, a); a = fmaf(h2[5], w1.y, a);
                o[j] = a;
            }

            // ---- store 24B (3x STG.64), rows contiguous across the warp ----
            float2* op = reinterpret_cast<float2*>(out + (size_t)row * OUT_DIM);
            op[0] = make_float2(o[0], o[1]);
            op[1] = make_float2(o[2], o[3]);
            op[2] = make_float2(o[4], o[5]);
        }
        __syncthreads();   // protect cur buf before it is restaged
    }
}

extern "C" void kernel_launch(void* const* d_in, const int* in_sizes, int n_in,
                              void* d_out, int out_size)
{
    const float* x  = (const float*)d_in[0];
    const float* W1 = (const float*)d_in[1];
    const float* W2 = (const float*)d_in[2];
    const float* W5 = (const float*)d_in[3];
    float* out = (float*)d_out;

    const int B = in_sizes[0] / IN_DIM;
    const int ntiles = (B + TILE_ROWS - 1) / TILE_ROWS;

    int blocks = 148 * 3;                 // persistent: 3 CTAs/SM on 148 SMs
    if (blocks > ntiles) blocks = ntiles;
    if (blocks < 1) blocks = 1;

    mlp3_kernel<<<blocks, THREADS>>>(x, W1, W2, W5, out, B, ntiles);
}

// round 3
// speedup vs baseline: 1.7037x; 1.1416x over previous
#include <cuda_runtime.h>

#define IN_DIM    20
#define HID       6
#define OUT_DIM   6
#define THREADS   256
#define ROWS_PT   2
#define TILE_ROWS (THREADS * ROWS_PT)          // 512
#define TILE_F4   (TILE_ROWS * IN_DIM / 4)     // 2560 float4 per tile
#define F4_PT     (TILE_F4 / THREADS)          // 10 per thread

__device__ __forceinline__ unsigned smem_u32(const void* p) {
    return (unsigned)__cvta_generic_to_shared(p);
}
__device__ __forceinline__ void cp16(unsigned dst, const void* src) {
    asm volatile("cp.async.ca.shared.global [%0], [%1], 16;\n" :: "r"(dst), "l"(src));
}
__device__ __forceinline__ void cp_commit() {
    asm volatile("cp.async.commit_group;\n" ::: "memory");
}
template <int N>
__device__ __forceinline__ void cp_wait() {
    asm volatile("cp.async.wait_group %0;\n" :: "n"(N) : "memory");
}

// sigmoid(z) = 0.5 * tanh(0.5 z) + 0.5   -> 1 MUFU.TANH + FMUL + FFMA
__device__ __forceinline__ float sigmoid_t(float z) {
    float th;
    asm("tanh.approx.f32 %0, %1;" : "=f"(th) : "f"(z * 0.5f));
    return fmaf(th, 0.5f, 0.5f);
}

__global__ __launch_bounds__(THREADS, 2)
void mlp3_kernel(const float* __restrict__ x,
                 const float* __restrict__ W1,   // [HID, IN]
                 const float* __restrict__ W2,   // [HID, HID]
                 const float* __restrict__ W5,   // [OUT, HID]
                 float* __restrict__ out,        // [B, OUT]
                 int B, int ntiles)
{
    __shared__ __align__(16) float sW1[HID * IN_DIM];
    __shared__ __align__(16) float sW2[HID * 8];
    __shared__ __align__(16) float sW5[OUT_DIM * 8];
    extern __shared__ __align__(16) float sX[];   // [2][TILE_ROWS * IN_DIM]

    const int t = threadIdx.x;

    if (t < HID * IN_DIM) sW1[t] = W1[t];
    if (t < HID * 8)      sW2[t] = ((t & 7) < HID) ? W2[(t >> 3) * HID + (t & 7)] : 0.0f;
    if (t < OUT_DIM * 8)  sW5[t] = ((t & 7) < HID) ? W5[(t >> 3) * HID + (t & 7)] : 0.0f;

    const size_t total_f4 = ((size_t)B * IN_DIM) >> 2;

    auto stage = [&](int tile, int buf) {
        size_t base_f4 = (size_t)tile * TILE_F4;
        const float4* src = reinterpret_cast<const float4*>(x) + base_f4;
        unsigned dst = smem_u32(&sX[(size_t)buf * (TILE_ROWS * IN_DIM)]);
#pragma unroll
        for (int q = 0; q < F4_PT; ++q) {
            int idx = t + q * THREADS;
            if (base_f4 + (size_t)idx < total_f4)
                cp16(dst + (unsigned)idx * 16, src + idx);
        }
    };

    int tile = blockIdx.x;
    if (tile < ntiles) stage(tile, 0);
    cp_commit();
    __syncthreads();

    int buf = 0;
    for (; tile < ntiles; tile += gridDim.x, buf ^= 1) {
        int nxt = tile + gridDim.x;
        if (nxt < ntiles) stage(nxt, buf ^ 1);
        cp_commit();
        cp_wait<1>();
        __syncthreads();

        const float* xb = &sX[(size_t)buf * (TILE_ROWS * IN_DIM)];
        const int r0 = tile * TILE_ROWS + t;          // row A
        const int r1 = r0 + THREADS;                  // row B

        // ---- load both rows from smem: 2 x 5 LDS.128, conflict-free ----
        float4 xa[5], xbv[5];
        const float4* pa = reinterpret_cast<const float4*>(&xb[t * IN_DIM]);
        const float4* pb = reinterpret_cast<const float4*>(&xb[(t + THREADS) * IN_DIM]);
#pragma unroll
        for (int q = 0; q < 5; ++q) { xa[q] = pa[q]; xbv[q] = pb[q]; }

        // ---- layer 1 (weights shared across both rows) ----
        float h1a[6], h1b[6];
#pragma unroll
        for (int j = 0; j < HID; ++j) {
            const float4* wr = reinterpret_cast<const float4*>(&sW1[j * IN_DIM]);
            float a = 0.0f, b = 0.0f;
#pragma unroll
            for (int q = 0; q < 5; ++q) {
                float4 w = wr[q];
                a = fmaf(xa[q].x,  w.x, a); b = fmaf(xbv[q].x, w.x, b);
                a = fmaf(xa[q].y,  w.y, a); b = fmaf(xbv[q].y, w.y, b);
                a = fmaf(xa[q].z,  w.z, a); b = fmaf(xbv[q].z, w.z, b);
                a = fmaf(xa[q].w,  w.w, a); b = fmaf(xbv[q].w, w.w, b);
            }
            h1a[j] = sigmoid_t(a);
            h1b[j] = sigmoid_t(b);
        }

        // ---- layer 2 ----
        float h2a[6], h2b[6];
#pragma unroll
        for (int j = 0; j < HID; ++j) {
            const float4* wr = reinterpret_cast<const float4*>(&sW2[j * 8]);
            float4 w0 = wr[0], w1 = wr[1];
            float a = 0.0f, b = 0.0f;
            a = fmaf(h1a[0], w0.x, a); b = fmaf(h1b[0], w0.x, b);
            a = fmaf(h1a[1], w0.y, a); b = fmaf(h1b[1], w0.y, b);
            a = fmaf(h1a[2], w0.z, a); b = fmaf(h1b[2], w0.z, b);
            a = fmaf(h1a[3], w0.w, a); b = fmaf(h1b[3], w0.w, b);
            a = fmaf(h1a[4], w1.x, a); b = fmaf(h1b[4], w1.x, b);
            a = fmaf(h1a[5], w1.y, a); b = fmaf(h1b[5], w1.y, b);
            h2a[j] = sigmoid_t(a);
            h2b[j] = sigmoid_t(b);
        }

        // ---- layer 3 (linear) ----
        float oa[OUT_DIM], ob[OUT_DIM];
#pragma unroll
        for (int j = 0; j < OUT_DIM; ++j) {
            const float4* wr = reinterpret_cast<const float4*>(&sW5[j * 8]);
            float4 w0 = wr[0], w1 = wr[1];
            float a = 0.0f, b = 0.0f;
            a = fmaf(h2a[0], w0.x, a); b = fmaf(h2b[0], w0.x, b);
            a = fmaf(h2a[1], w0.y, a); b = fmaf(h2b[1], w0.y, b);
            a = fmaf(h2a[2], w0.z, a); b = fmaf(h2b[2], w0.z, b);
            a = fmaf(h2a[3], w0.w, a); b = fmaf(h2b[3], w0.w, b);
            a = fmaf(h2a[4], w1.x, a); b = fmaf(h2b[4], w1.x, b);
            a = fmaf(h2a[5], w1.y, a); b = fmaf(h2b[5], w1.y, b);
            oa[j] = a; ob[j] = b;
        }

        if (r0 < B) {
            float2* op = reinterpret_cast<float2*>(out + (size_t)r0 * OUT_DIM);
            op[0] = make_float2(oa[0], oa[1]);
            op[1] = make_float2(oa[2], oa[3]);
            op[2] = make_float2(oa[4], oa[5]);
        }
        if (r1 < B) {
            float2* op = reinterpret_cast<float2*>(out + (size_t)r1 * OUT_DIM);
            op[0] = make_float2(ob[0], ob[1]);
            op[1] = make_float2(ob[2], ob[3]);
            op[2] = make_float2(ob[4], ob[5]);
        }
        __syncthreads();
    }
}

extern "C" void kernel_launch(void* const* d_in, const int* in_sizes, int n_in,
                              void* d_out, int out_size)
{
    const float* x  = (const float*)d_in[0];
    const float* W1 = (const float*)d_in[1];
    const float* W2 = (const float*)d_in[2];
    const float* W5 = (const float*)d_in[3];
    float* out = (float*)d_out;

    const int B = in_sizes[0] / IN_DIM;
    const int ntiles = (B + TILE_ROWS - 1) / TILE_ROWS;

    const size_t smem_bytes = 2ull * TILE_ROWS * IN_DIM * sizeof(float);  // 80 KB
    static bool attr_set = false;
    if (!attr_set) {
        cudaFuncSetAttribute(mlp3_kernel,
                             cudaFuncAttributeMaxDynamicSharedMemorySize,
                             (int)smem_bytes);
        attr_set = true;
    }

    int blocks = 148 * 2;                 // persistent: 2 CTAs/SM
    if (blocks > ntiles) blocks = ntiles;
    if (blocks < 1) blocks = 1;

    mlp3_kernel<<<blocks, THREADS, smem_bytes>>>(x, W1, W2, W5, out, B, ntiles);
}

// round 4
// speedup vs baseline: 1.7777x; 1.0434x over previous
#include <cuda_runtime.h>

#define IN_DIM    20
#define HID       6
#define OUT_DIM   6
#define THREADS   128
#define ROWS_PT   2
#define TILE_ROWS (THREADS * ROWS_PT)          // 256
#define TILE_F4   (TILE_ROWS * IN_DIM / 4)     // 1280 float4 per tile
#define F4_PT     (TILE_F4 / THREADS)          // 10 per thread

__device__ __forceinline__ unsigned smem_u32(const void* p) {
    return (unsigned)__cvta_generic_to_shared(p);
}
__device__ __forceinline__ void cp16(unsigned dst, const void* src) {
    // .cg: bypass L1, straight to smem — x is read-once streaming data
    asm volatile("cp.async.cg.shared.global [%0], [%1], 16;\n" :: "r"(dst), "l"(src));
}
__device__ __forceinline__ void cp_commit() {
    asm volatile("cp.async.commit_group;\n" ::: "memory");
}
template <int N>
__device__ __forceinline__ void cp_wait() {
    asm volatile("cp.async.wait_group %0;\n" :: "n"(N) : "memory");
}
__device__ __forceinline__ void stg_cs_v2(float2* p, float2 v) {
    asm volatile("st.global.cs.v2.f32 [%0], {%1, %2};\n" :: "l"(p), "f"(v.x), "f"(v.y));
}

// sigmoid(z) = 0.5 * tanh(0.5 z) + 0.5   -> 1 MUFU.TANH + FMUL + FFMA
__device__ __forceinline__ float sigmoid_t(float z) {
    float th;
    asm("tanh.approx.f32 %0, %1;" : "=f"(th) : "f"(z * 0.5f));
    return fmaf(th, 0.5f, 0.5f);
}

__global__ __launch_bounds__(THREADS, 5)
void mlp3_kernel(const float* __restrict__ x,
                 const float* __restrict__ W1,   // [HID, IN]
                 const float* __restrict__ W2,   // [HID, HID]
                 const float* __restrict__ W5,   // [OUT, HID]
                 float* __restrict__ out,        // [B, OUT]
                 int B, int ntiles)
{
    __shared__ __align__(16) float sW1[HID * IN_DIM];
    __shared__ __align__(16) float sW2[HID * 8];
    __shared__ __align__(16) float sW5[OUT_DIM * 8];
    extern __shared__ __align__(16) float sX[];   // [2][TILE_ROWS * IN_DIM]

    const int t = threadIdx.x;

    if (t < HID * IN_DIM) sW1[t] = W1[t];
    if (t < HID * 8)      sW2[t] = ((t & 7) < HID) ? W2[(t >> 3) * HID + (t & 7)] : 0.0f;
    if (t < OUT_DIM * 8)  sW5[t] = ((t & 7) < HID) ? W5[(t >> 3) * HID + (t & 7)] : 0.0f;

    const size_t total_f4 = ((size_t)B * IN_DIM) >> 2;

    auto stage = [&](int tile, int buf) {
        size_t base_f4 = (size_t)tile * TILE_F4;
        const float4* src = reinterpret_cast<const float4*>(x) + base_f4;
        unsigned dst = smem_u32(&sX[(size_t)buf * (TILE_ROWS * IN_DIM)]);
#pragma unroll
        for (int q = 0; q < F4_PT; ++q) {
            int idx = t + q * THREADS;
            if (base_f4 + (size_t)idx < total_f4)
                cp16(dst + (unsigned)idx * 16, src + idx);
        }
    };

    int tile = blockIdx.x;
    if (tile < ntiles) stage(tile, 0);
    cp_commit();
    __syncthreads();

    int buf = 0;
    for (; tile < ntiles; tile += gridDim.x, buf ^= 1) {
        int nxt = tile + gridDim.x;
        if (nxt < ntiles) stage(nxt, buf ^ 1);
        cp_commit();
        cp_wait<1>();
        __syncthreads();

        const float* xb = &sX[(size_t)buf * (TILE_ROWS * IN_DIM)];
        const int r0 = tile * TILE_ROWS + t;          // row A
        const int r1 = r0 + THREADS;                  // row B

        // ---- load both rows from smem: 2 x 5 LDS.128, conflict-free ----
        float4 xa[5], xbv[5];
        const float4* pa = reinterpret_cast<const float4*>(&xb[t * IN_DIM]);
        const float4* pb = reinterpret_cast<const float4*>(&xb[(t + THREADS) * IN_DIM]);
#pragma unroll
        for (int q = 0; q < 5; ++q) { xa[q] = pa[q]; xbv[q] = pb[q]; }

        // ---- layer 1 (weights shared across both rows) ----
        float h1a[6], h1b[6];
#pragma unroll
        for (int j = 0; j < HID; ++j) {
            const float4* wr = reinterpret_cast<const float4*>(&sW1[j * IN_DIM]);
            float a = 0.0f, b = 0.0f;
#pragma unroll
            for (int q = 0; q < 5; ++q) {
                float4 w = wr[q];
                a = fmaf(xa[q].x,  w.x, a); b = fmaf(xbv[q].x, w.x, b);
                a = fmaf(xa[q].y,  w.y, a); b = fmaf(xbv[q].y, w.y, b);
                a = fmaf(xa[q].z,  w.z, a); b = fmaf(xbv[q].z, w.z, b);
                a = fmaf(xa[q].w,  w.w, a); b = fmaf(xbv[q].w, w.w, b);
            }
            h1a[j] = sigmoid_t(a);
            h1b[j] = sigmoid_t(b);
        }

        // ---- layer 2 ----
        float h2a[6], h2b[6];
#pragma unroll
        for (int j = 0; j < HID; ++j) {
            const float4* wr = reinterpret_cast<const float4*>(&sW2[j * 8]);
            float4 w0 = wr[0], w1 = wr[1];
            float a = 0.0f, b = 0.0f;
            a = fmaf(h1a[0], w0.x, a); b = fmaf(h1b[0], w0.x, b);
            a = fmaf(h1a[1], w0.y, a); b = fmaf(h1b[1], w0.y, b);
            a = fmaf(h1a[2], w0.z, a); b = fmaf(h1b[2], w0.z, b);
            a = fmaf(h1a[3], w0.w, a); b = fmaf(h1b[3], w0.w, b);
            a = fmaf(h1a[4], w1.x, a); b = fmaf(h1b[4], w1.x, b);
            a = fmaf(h1a[5], w1.y, a); b = fmaf(h1b[5], w1.y, b);
            h2a[j] = sigmoid_t(a);
            h2b[j] = sigmoid_t(b);
        }

        // ---- layer 3 (linear) ----
        float oa[OUT_DIM], ob[OUT_DIM];
#pragma unroll
        for (int j = 0; j < OUT_DIM; ++j) {
            const float4* wr = reinterpret_cast<const float4*>(&sW5[j * 8]);
            float4 w0 = wr[0], w1 = wr[1];
            float a = 0.0f, b = 0.0f;
            a = fmaf(h2a[0], w0.x, a); b = fmaf(h2b[0], w0.x, b);
            a = fmaf(h2a[1], w0.y, a); b = fmaf(h2b[1], w0.y, b);
            a = fmaf(h2a[2], w0.z, a); b = fmaf(h2b[2], w0.z, b);
            a = fmaf(h2a[3], w0.w, a); b = fmaf(h2b[3], w0.w, b);
            a = fmaf(h2a[4], w1.x, a); b = fmaf(h2b[4], w1.x, b);
            a = fmaf(h2a[5], w1.y, a); b = fmaf(h2b[5], w1.y, b);
            oa[j] = a; ob[j] = b;
        }

        if (r0 < B) {
            float2* op = reinterpret_cast<float2*>(out + (size_t)r0 * OUT_DIM);
            stg_cs_v2(op + 0, make_float2(oa[0], oa[1]));
            stg_cs_v2(op + 1, make_float2(oa[2], oa[3]));
            stg_cs_v2(op + 2, make_float2(oa[4], oa[5]));
        }
        if (r1 < B) {
            float2* op = reinterpret_cast<float2*>(out + (size_t)r1 * OUT_DIM);
            stg_cs_v2(op + 0, make_float2(ob[0], ob[1]));
            stg_cs_v2(op + 1, make_float2(ob[2], ob[3]));
            stg_cs_v2(op + 2, make_float2(ob[4], ob[5]));
        }
        __syncthreads();
    }
}

extern "C" void kernel_launch(void* const* d_in, const int* in_sizes, int n_in,
                              void* d_out, int out_size)
{
    const float* x  = (const float*)d_in[0];
    const float* W1 = (const float*)d_in[1];
    const float* W2 = (const float*)d_in[2];
    const float* W5 = (const float*)d_in[3];
    float* out = (float*)d_out;

    const int B = in_sizes[0] / IN_DIM;
    const int ntiles = (B + TILE_ROWS - 1) / TILE_ROWS;

    const size_t smem_bytes = 2ull * TILE_ROWS * IN_DIM * sizeof(float);  // 40 KB
    static bool attr_set = false;
    if (!attr_set) {
        cudaFuncSetAttribute(mlp3_kernel,
                             cudaFuncAttributeMaxDynamicSharedMemorySize,
                             (int)smem_bytes);
        attr_set = true;
    }

    int blocks = 148 * 5;                 // persistent: 5 CTAs/SM
    if (blocks > ntiles) blocks = ntiles;
    if (blocks < 1) blocks = 1;

    mlp3_kernel<<<blocks, THREADS, smem_bytes>>>(x, W1, W2, W5, out, B, ntiles);
}